// round 1
// baseline (speedup 1.0000x reference)
#include <cuda_runtime.h>
#include <math.h>

#define NF 96
#define GD 12
#define K2T 9
#define BN 4
#define HH 128
#define WW 128
#define HWSZ (HH*WW)

// ---------------- scratch (device globals; no runtime allocation) ------------
__device__ float g_t1[BN*NF*HWSZ];            // oc1 out, later c1 out
__device__ float g_t2[BN*NF*HWSZ];            // oc3 out
__device__ float g_e1[BN*NF*64*64];           // e1 out
__device__ float g_d1[BN*NF*64*64];           // d1 out
__device__ float g_off[BN*2*GD*K2T*HWSZ];     // offset conv out (216 ch)
__device__ float g_S[BN*NF*K2T*HWSZ];         // DCN sampled tensor (864 "ch")

// ---------------- generic 3x3 stride-1 conv, H=W=128 -------------------------
// tile 64x16 output, 256 threads, each thread: 4 adjacent x-pixels x 8 oc.
// flags: bit0 = LReLU, bit1 = add into out (out += v)
__global__ __launch_bounds__(256) void conv3x3_s1(
    const float* __restrict__ inA, int cinA,
    const float* __restrict__ inB, int cinB,
    const float* __restrict__ w, const float* __restrict__ bias,
    float* __restrict__ out, int cout, int flags)
{
    const int tid = threadIdx.x;
    const int tx = tid & 15;      // 0..15 -> x group of 4
    const int ty = tid >> 4;      // 0..15 -> y row
    const int x0 = (blockIdx.x & 1) * 64;
    const int y0 = (blockIdx.x >> 1) * 16;
    const int ocb = blockIdx.y * 8;
    const int n = blockIdx.z;
    const int cin = cinA + cinB;

    __shared__ float sIn[4][18][67];
    __shared__ float sW[8][4][9];

    float acc[8][4];
#pragma unroll
    for (int o = 0; o < 8; o++)
#pragma unroll
        for (int j = 0; j < 4; j++) acc[o][j] = 0.f;

    for (int ic0 = 0; ic0 < cin; ic0 += 4) {
        __syncthreads();
        // load 4 x 18 x 66 input halo (zero padded)
        for (int idx = tid; idx < 4*18*66; idx += 256) {
            int ic = idx / (18*66);
            int r  = (idx / 66) % 18;
            int c  = idx % 66;
            int gy = y0 - 1 + r;
            int gx = x0 - 1 + c;
            float v = 0.f;
            if ((unsigned)gy < (unsigned)HH && (unsigned)gx < (unsigned)WW) {
                int icg = ic0 + ic;
                const float* p = (icg < cinA)
                    ? (inA + ((size_t)(n*cinA + icg)*HH + gy)*WW + gx)
                    : (inB + ((size_t)(n*cinB + (icg - cinA))*HH + gy)*WW + gx);
                v = *p;
            }
            sIn[ic][r][c] = v;
        }
        // load 8 oc x 4 ic x 9 weights
        for (int idx = tid; idx < 8*4*9; idx += 256) {
            int o  = idx / 36;
            int ic = (idx / 9) % 4;
            int t  = idx % 9;
            sW[o][ic][t] = w[((size_t)(ocb + o)*cin + ic0 + ic)*9 + t];
        }
        __syncthreads();

#pragma unroll
        for (int ic = 0; ic < 4; ic++) {
#pragma unroll
            for (int dy = 0; dy < 3; dy++) {
                float v[6];
#pragma unroll
                for (int j = 0; j < 6; j++) v[j] = sIn[ic][ty + dy][4*tx + j];
#pragma unroll
                for (int dx = 0; dx < 3; dx++) {
                    float wv[8];
#pragma unroll
                    for (int o = 0; o < 8; o++) wv[o] = sW[o][ic][dy*3 + dx];
#pragma unroll
                    for (int j = 0; j < 4; j++) {
                        float xv = v[j + dx];
#pragma unroll
                        for (int o = 0; o < 8; o++)
                            acc[o][j] = fmaf(wv[o], xv, acc[o][j]);
                    }
                }
            }
        }
    }

    const int y = y0 + ty;
#pragma unroll
    for (int o = 0; o < 8; o++) {
        float bv = bias[ocb + o];
#pragma unroll
        for (int j = 0; j < 4; j++) {
            float v = acc[o][j] + bv;
            if (flags & 1) v = (v >= 0.f) ? v : 0.1f * v;
            size_t oi = ((size_t)(n*cout + ocb + o)*HH + y)*WW + (x0 + 4*tx + j);
            if (flags & 2) out[oi] += v; else out[oi] = v;
        }
    }
}

// ---------------- 3x3 stride-2 conv (SAME: pad_lo=0, pad_hi=1) ---------------
// cin = cout = 96. out tile 16x16, 8 oc per thread. Optional rounded copy (q).
__global__ __launch_bounds__(256) void conv3x3_s2(
    const float* __restrict__ in, int Hin,
    const float* __restrict__ w, const float* __restrict__ bias,
    float* __restrict__ out, float* __restrict__ out_q, int flags)
{
    const int tid = threadIdx.x;
    const int tx = tid & 15;
    const int ty = tid >> 4;
    const int Hout = Hin >> 1;
    const int tilesX = Hout >> 4;
    const int x0 = (blockIdx.x % tilesX) * 16;
    const int y0 = (blockIdx.x / tilesX) * 16;
    const int ocb = blockIdx.y * 8;
    const int n = blockIdx.z;

    __shared__ float sIn[2][33][34];
    __shared__ float sW[8][2][9];

    float acc[8];
#pragma unroll
    for (int o = 0; o < 8; o++) acc[o] = 0.f;

    for (int ic0 = 0; ic0 < NF; ic0 += 2) {
        __syncthreads();
        for (int idx = tid; idx < 2*33*33; idx += 256) {
            int ic = idx / (33*33);
            int r  = (idx / 33) % 33;
            int c  = idx % 33;
            int gy = 2*y0 + r;
            int gx = 2*x0 + c;
            float v = 0.f;
            if (gy < Hin && gx < Hin) {
                v = in[((size_t)(n*NF + ic0 + ic)*Hin + gy)*Hin + gx];
            }
            sIn[ic][r][c] = v;
        }
        for (int idx = tid; idx < 8*2*9; idx += 256) {
            int o  = idx / 18;
            int ic = (idx / 9) % 2;
            int t  = idx % 9;
            sW[o][ic][t] = w[((size_t)(ocb + o)*NF + ic0 + ic)*9 + t];
        }
        __syncthreads();

#pragma unroll
        for (int ic = 0; ic < 2; ic++) {
#pragma unroll
            for (int dy = 0; dy < 3; dy++) {
#pragma unroll
                for (int dx = 0; dx < 3; dx++) {
                    float xv = sIn[ic][2*ty + dy][2*tx + dx];
#pragma unroll
                    for (int o = 0; o < 8; o++)
                        acc[o] = fmaf(sW[o][ic][dy*3 + dx], xv, acc[o]);
                }
            }
        }
    }

#pragma unroll
    for (int o = 0; o < 8; o++) {
        float v = acc[o] + bias[ocb + o];
        if (flags & 1) v = (v >= 0.f) ? v : 0.1f * v;
        size_t oi = ((size_t)(n*NF + ocb + o)*Hout + (y0 + ty))*Hout + (x0 + tx);
        out[oi] = v;
        if (out_q) out_q[oi] = rintf(v);   // round half to even == jnp.round
    }
}

// ---------------- 3x3 stride-2 transpose conv (2x upsample) ------------------
// jax conv_transpose SAME, k=3, s=2 -> lhs_dilation=2, pad=(2,1), no kernel flip.
// Output parity decomposition: even/even uses taps {0,2}x{0,2}; even/odd {0,2}x{1};
// odd/even {1}x{0,2}; odd/odd {1}x{1}. out tile 32x32, 8 oc per thread.
__global__ __launch_bounds__(256) void deconv3x3_x2(
    const float* __restrict__ in, int Hin,
    const float* __restrict__ w, const float* __restrict__ bias,
    float* __restrict__ out, int flags)
{
    const int tid = threadIdx.x;
    const int tx = tid & 15;
    const int ty = tid >> 4;
    const int Hout = Hin * 2;
    const int tilesX = Hout >> 5;
    const int tX = blockIdx.x % tilesX;
    const int tY = blockIdx.x / tilesX;
    const int xin0 = tX * 16, yin0 = tY * 16;
    const int x0o = tX * 32, y0o = tY * 32;
    const int ocb = blockIdx.y * 8;
    const int n = blockIdx.z;

    __shared__ float sIn[4][17][18];
    __shared__ float sW[8][4][9];

    float aEE[8], aEO[8], aOE[8], aOO[8];
#pragma unroll
    for (int o = 0; o < 8; o++) { aEE[o]=0.f; aEO[o]=0.f; aOE[o]=0.f; aOO[o]=0.f; }

    for (int ic0 = 0; ic0 < NF; ic0 += 4) {
        __syncthreads();
        for (int idx = tid; idx < 4*17*17; idx += 256) {
            int ic = idx / (17*17);
            int r  = (idx / 17) % 17;
            int c  = idx % 17;
            int gy = yin0 - 1 + r;
            int gx = xin0 - 1 + c;
            float v = 0.f;
            if ((unsigned)gy < (unsigned)Hin && (unsigned)gx < (unsigned)Hin) {
                v = in[((size_t)(n*NF + ic0 + ic)*Hin + gy)*Hin + gx];
            }
            sIn[ic][r][c] = v;
        }
        for (int idx = tid; idx < 8*4*9; idx += 256) {
            int o  = idx / 36;
            int ic = (idx / 9) % 4;
            int t  = idx % 9;
            sW[o][ic][t] = w[((size_t)(ocb + o)*NF + ic0 + ic)*9 + t];
        }
        __syncthreads();

#pragma unroll
        for (int ic = 0; ic < 4; ic++) {
            float v00 = sIn[ic][ty    ][tx    ];
            float v01 = sIn[ic][ty    ][tx + 1];
            float v10 = sIn[ic][ty + 1][tx    ];
            float v11 = sIn[ic][ty + 1][tx + 1];
#pragma unroll
            for (int o = 0; o < 8; o++) {
                const float* wp = &sW[o][ic][0];
                aEE[o] = fmaf(wp[0], v00, aEE[o]);
                aEE[o] = fmaf(wp[2], v01, aEE[o]);
                aEE[o] = fmaf(wp[6], v10, aEE[o]);
                aEE[o] = fmaf(wp[8], v11, aEE[o]);
                aEO[o] = fmaf(wp[1], v01, aEO[o]);
                aEO[o] = fmaf(wp[7], v11, aEO[o]);
                aOE[o] = fmaf(wp[3], v10, aOE[o]);
                aOE[o] = fmaf(wp[5], v11, aOE[o]);
                aOO[o] = fmaf(wp[4], v11, aOO[o]);
            }
        }
    }

    const int ye = y0o + 2*ty, xe = x0o + 2*tx;
#pragma unroll
    for (int o = 0; o < 8; o++) {
        float bv = bias[ocb + o];
        float vEE = aEE[o] + bv, vEO = aEO[o] + bv, vOE = aOE[o] + bv, vOO = aOO[o] + bv;
        if (flags & 1) {
            vEE = (vEE >= 0.f) ? vEE : 0.1f*vEE;
            vEO = (vEO >= 0.f) ? vEO : 0.1f*vEO;
            vOE = (vOE >= 0.f) ? vOE : 0.1f*vOE;
            vOO = (vOO >= 0.f) ? vOO : 0.1f*vOO;
        }
        size_t base = ((size_t)(n*NF + ocb + o)*Hout + ye)*Hout + xe;
        out[base]            = vEE;
        out[base + 1]        = vEO;
        out[base + Hout]     = vOE;
        out[base + Hout + 1] = vOO;
    }
}

// ---------------- DCNv1 bilinear sampling -------------------------------------
// one thread per (n, g, tap, pixel); handles the 8 channels of its group.
__global__ __launch_bounds__(256) void dcn_sample(
    const float* __restrict__ ref, const float* __restrict__ off,
    float* __restrict__ S)
{
    int idx = blockIdx.x * 256 + threadIdx.x;
    if (idx >= BN*GD*K2T*HWSZ) return;
    int p = idx & (HWSZ - 1);
    int t = idx >> 14;
    int k = t % 9;  t /= 9;
    int g = t % GD;
    int n = t / GD;
    int y = p >> 7, x = p & 127;

    int offc = (g*9 + k)*2;
    float dy = off[((size_t)(n*2*GD*K2T + offc    ))*HWSZ + p];
    float dx = off[((size_t)(n*2*GD*K2T + offc + 1))*HWSZ + p];
    float py = (float)y + (float)(k/3 - 1) + dy;
    float px = (float)x + (float)(k%3 - 1) + dx;
    float fy = floorf(py), fx = floorf(px);
    float wy = py - fy, wx = px - fx;
    int iy = (int)fy, ix = (int)fx;

    float wgt[4]; int ofs[4];
#pragma unroll
    for (int r = 0; r < 2; r++) {
#pragma unroll
        for (int c = 0; c < 2; c++) {
            int yy = iy + r, xx = ix + c;
            bool val = ((unsigned)yy < (unsigned)HH) && ((unsigned)xx < (unsigned)WW);
            float wv = (r ? wy : 1.f - wy) * (c ? wx : 1.f - wx);
            wgt[r*2 + c] = val ? wv : 0.f;
            ofs[r*2 + c] = val ? (yy*WW + xx) : 0;
        }
    }

    const float* base = ref + (size_t)(n*NF + g*8)*HWSZ;
    float* so = S + ((size_t)(n*NF + g*8)*9 + k)*HWSZ + p;
#pragma unroll
    for (int c = 0; c < 8; c++) {
        const float* bp = base + (size_t)c*HWSZ;
        float s = wgt[0]*bp[ofs[0]] + wgt[1]*bp[ofs[1]]
                + wgt[2]*bp[ofs[2]] + wgt[3]*bp[ofs[3]];
        so[(size_t)c*9*HWSZ] = s;
    }
}

// ---------------- 1x1 conv / GEMM: out[96, HW] = W[96,864] * S[864, HW] ------
// tile: 256 pixels x 32 oc; thread: 4 pixels (stride 64) x 8 oc.
__global__ __launch_bounds__(256) void conv1x1(
    const float* __restrict__ S, const float* __restrict__ w,
    const float* __restrict__ bias, float* __restrict__ out)
{
    const int tid = threadIdx.x;
    const int tpx = tid & 63;
    const int to  = tid >> 6;          // 0..3
    const int p0  = blockIdx.x * 256;
    const int ocb = blockIdx.y * 32;
    const int n   = blockIdx.z;
    const int CIN = NF * K2T;          // 864

    __shared__ float sS[8][256];
    __shared__ float sW[32][8];

    float acc[8][4];
#pragma unroll
    for (int o = 0; o < 8; o++)
#pragma unroll
        for (int j = 0; j < 4; j++) acc[o][j] = 0.f;

    for (int ic0 = 0; ic0 < CIN; ic0 += 8) {
        __syncthreads();
#pragma unroll
        for (int ic = 0; ic < 8; ic++)
            sS[ic][tid] = S[((size_t)(n*CIN + ic0 + ic))*HWSZ + p0 + tid];
        {
            int o = tid >> 3, ic = tid & 7;
            sW[o][ic] = w[(size_t)(ocb + o)*CIN + ic0 + ic];
        }
        __syncthreads();

#pragma unroll
        for (int ic = 0; ic < 8; ic++) {
            float xv[4];
#pragma unroll
            for (int j = 0; j < 4; j++) xv[j] = sS[ic][tpx + 64*j];
            float wv[8];
#pragma unroll
            for (int o = 0; o < 8; o++) wv[o] = sW[to*8 + o][ic];
#pragma unroll
            for (int o = 0; o < 8; o++)
#pragma unroll
                for (int j = 0; j < 4; j++)
                    acc[o][j] = fmaf(wv[o], xv[j], acc[o][j]);
        }
    }

#pragma unroll
    for (int o = 0; o < 8; o++) {
        float bv = bias[ocb + to*8 + o];
#pragma unroll
        for (int j = 0; j < 4; j++) {
            out[((size_t)(n*NF + ocb + to*8 + o))*HWSZ + p0 + tpx + 64*j] = acc[o][j] + bv;
        }
    }
}

// ------------------------------ launch ---------------------------------------
extern "C" void kernel_launch(void* const* d_in, const int* in_sizes, int n_in,
                              void* d_out, int out_size)
{
    const float* ref   = (const float*)d_in[0];
    const float* inp   = (const float*)d_in[1];
    const float* w_oc1 = (const float*)d_in[2];  const float* b_oc1 = (const float*)d_in[3];
    const float* w_oc3 = (const float*)d_in[4];  const float* b_oc3 = (const float*)d_in[5];
    const float* w_e1  = (const float*)d_in[6];  const float* b_e1  = (const float*)d_in[7];
    const float* w_e2  = (const float*)d_in[8];  const float* b_e2  = (const float*)d_in[9];
    const float* w_d1  = (const float*)d_in[10]; const float* b_d1  = (const float*)d_in[11];
    const float* w_d2  = (const float*)d_in[12]; const float* b_d2  = (const float*)d_in[13];
    const float* w_off = (const float*)d_in[14]; const float* b_off = (const float*)d_in[15];
    const float* w_dcn = (const float*)d_in[16]; const float* b_dcn = (const float*)d_in[17];
    const float* w_c1  = (const float*)d_in[18]; const float* b_c1  = (const float*)d_in[19];
    const float* w_c2  = (const float*)d_in[20]; const float* b_c2  = (const float*)d_in[21];

    float* out  = (float*)d_out;
    float* oL1  = out;                                  // [4,96,128,128]
    float* oEN  = out + (size_t)BN*NF*HWSZ;             // [4,96,32,32]
    float* oQ   = oEN + (size_t)BN*NF*32*32;            // [4,96,32,32]
    float* oDEC = oQ  + (size_t)BN*NF*32*32;            // [4,96,128,128]

    float *t1, *t2, *e1b, *d1b, *offb, *Sb;
    cudaGetSymbolAddress((void**)&t1,   g_t1);
    cudaGetSymbolAddress((void**)&t2,   g_t2);
    cudaGetSymbolAddress((void**)&e1b,  g_e1);
    cudaGetSymbolAddress((void**)&d1b,  g_d1);
    cudaGetSymbolAddress((void**)&offb, g_off);
    cudaGetSymbolAddress((void**)&Sb,   g_S);

    // t = lrelu(conv(concat(ref, inp), oc1)); t = lrelu(conv(t, oc3))
    conv3x3_s1<<<dim3(16, 12, BN), 256>>>(ref, NF, inp, NF, w_oc1, b_oc1, t1, NF, 1);
    conv3x3_s1<<<dim3(16, 12, BN), 256>>>(t1, NF, nullptr, 0, w_oc3, b_oc3, t2, NF, 1);
    // encoder: e1 (stride2 + lrelu), e2 (stride2) -> en, q=round(en)
    conv3x3_s2<<<dim3(16, 12, BN), 256>>>(t2, 128, w_e1, b_e1, e1b, nullptr, 1);
    conv3x3_s2<<<dim3(4,  12, BN), 256>>>(e1b, 64, w_e2, b_e2, oEN, oQ, 0);
    // decoder: two 2x transpose convs
    deconv3x3_x2<<<dim3(4,  12, BN), 256>>>(oQ,  32, w_d1, b_d1, d1b, 1);
    deconv3x3_x2<<<dim3(16, 12, BN), 256>>>(d1b, 64, w_d2, b_d2, oDEC, 0);
    // offset head (216 ch)
    conv3x3_s1<<<dim3(16, 27, BN), 256>>>(oDEC, NF, nullptr, 0, w_off, b_off, offb, 2*GD*K2T, 0);
    // deformable conv = bilinear sampling + 1x1 GEMM over 864 "channels"
    dcn_sample<<<(BN*GD*K2T*HWSZ)/256, 256>>>(ref, offb, Sb);
    conv1x1<<<dim3(HWSZ/256, 3, BN), 256>>>(Sb, w_dcn, b_dcn, oL1);
    // fusion tail: o = lrelu(conv(concat(L1, ref), c1)); o = lrelu(conv(o, c2)); L1 += o
    conv3x3_s1<<<dim3(16, 12, BN), 256>>>(oL1, NF, ref, NF, w_c1, b_c1, t1, NF, 1);
    conv3x3_s1<<<dim3(16, 12, BN), 256>>>(t1, NF, nullptr, 0, w_c2, b_c2, oL1, NF, 3);
}